// round 12
// baseline (speedup 1.0000x reference)
#include <cuda_runtime.h>
#include <cuda_fp16.h>
#include <cstdint>
#include <cstddef>

#define N_NODES 50000
#define K_EIG   512
#define F_DIM   128
#define CH      704       // 22 stages of 32 rows
#define NC      72        // 4 x 72 = 288 CTAs = one wave at 2 CTAs/SM
#define NST1    22

// phase1 smem (fp16 element units), SINGLE buffer
#define P1_STR  136                 // 272B row stride -> ldmatrix conflict-free
#define P1_ASZ  (32 * P1_STR)       // 4352 per 32x128 plane
#define P1_SMEM (3 * P1_ASZ * 2)    // UH, UL, XH = 26112 B

// phase2 smem: tile 64n x 128f, SINGLE buffer
#define P2_USTR 40
#define P2_USZ  (64 * P2_USTR)      // 2560
#define P2_YSTR 136
#define P2_YSZ  (32 * P2_YSTR)      // 4352
#define P2_SMEM ((2 * P2_USZ + P2_YSZ) * 2)   // 18944 B

__device__ float  g_partial[(size_t)NC * K_EIG * F_DIM];
__device__ __half g_yh[K_EIG * F_DIM];     // y rounded to fp16, [k][f]

// ---------------------------------------------------------------------------
__device__ __forceinline__ unsigned packh(__half a, __half b) {
    return ((unsigned)__half_as_ushort(b) << 16) | __half_as_ushort(a);
}

__device__ __forceinline__ void split2h(float a, float b, unsigned &hp, unsigned &lp) {
    __half ha = __float2half_rn(a);
    __half hb = __float2half_rn(b);
    __half la = __float2half_rn(a - __half2float(ha));
    __half lb = __float2half_rn(b - __half2float(hb));
    hp = packh(ha, hb);
    lp = packh(la, lb);
}

__device__ __forceinline__ void split4h(float4 v, uint2 &h, uint2 &l) {
    split2h(v.x, v.y, h.x, l.x);
    split2h(v.z, v.w, h.y, l.y);
}

__device__ __forceinline__ uint2 round4h(float4 v) {
    return make_uint2(packh(__float2half_rn(v.x), __float2half_rn(v.y)),
                      packh(__float2half_rn(v.z), __float2half_rn(v.w)));
}

#define LDSM_T(R, addr) \
    asm volatile("ldmatrix.sync.aligned.m8n8.x4.trans.shared.b16 {%0,%1,%2,%3}, [%4];" \
                 : "=r"((R)[0]), "=r"((R)[1]), "=r"((R)[2]), "=r"((R)[3]) : "r"(addr))

#define LDSM_N(R, addr) \
    asm volatile("ldmatrix.sync.aligned.m8n8.x4.shared.b16 {%0,%1,%2,%3}, [%4];" \
                 : "=r"((R)[0]), "=r"((R)[1]), "=r"((R)[2]), "=r"((R)[3]) : "r"(addr))

#define MMA16(C, A, B0, B1) \
    asm volatile("mma.sync.aligned.m16n8k16.row.col.f32.f16.f16.f32 " \
                 "{%0,%1,%2,%3},{%4,%5,%6,%7},{%8,%9},{%0,%1,%2,%3};" \
                 : "+f"((C)[0]), "+f"((C)[1]), "+f"((C)[2]), "+f"((C)[3]) \
                 : "r"((A)[0]), "r"((A)[1]), "r"((A)[2]), "r"((A)[3]), \
                   "r"(B0), "r"(B1))

// ---------------------------------------------------------------------------
// Phase 1: partial[ch][k][f] = sum_{n in chunk} U[n,k] * x[n,f]
// Grid (4,72)=288 CTAs, 256 thr, 2 CTAs/SM. A=U split fp16 hi/lo; B=x fp16.
// Single smem buffer, no reg prefetch — cross-CTA overlap hides latency.
// ---------------------------------------------------------------------------
__global__ void __launch_bounds__(256, 2)
phase1_kernel(const float* __restrict__ U, const float* __restrict__ x) {
    extern __shared__ unsigned short smw[];
    const unsigned sbase = (unsigned)__cvta_generic_to_shared(smw);

    const int kt   = blockIdx.x;
    const int ch   = blockIdx.y;
    const int tid  = threadIdx.x;
    const int lane = tid & 31;
    const int wid  = tid >> 5;
    const int wm   = wid >> 2;            // 0..1 (64 k-rows each)
    const int wf   = wid & 3;             // 0..3 (32 f each)
    const int n0   = ch * CH;

    int lrow[4], lcol[4];
    #pragma unroll
    for (int i = 0; i < 4; i++) {
        int e = tid + i * 256;
        lrow[i] = e >> 5;
        lcol[i] = (e & 31) << 2;
    }

    const int lr   = lane & 7;
    const int arow = ((lane >> 4) & 1) * 8 + lr;
    const int acol = ((lane >> 3) & 1) * 8;
    const int brow = ((lane >> 3) & 1) * 8 + lr;
    const int bcol = ((lane >> 4) & 1) * 8;
    unsigned aoffs[4], boffs[2];
    #pragma unroll
    for (int mt = 0; mt < 4; mt++)
        aoffs[mt] = arow * P1_STR + wm * 64 + mt * 16 + acol;
    #pragma unroll
    for (int blk = 0; blk < 2; blk++)
        boffs[blk] = brow * P1_STR + wf * 32 + blk * 16 + bcol;

    float acc[4][4][4];
    #pragma unroll
    for (int a = 0; a < 4; a++)
        #pragma unroll
        for (int b = 0; b < 4; b++)
            #pragma unroll
            for (int c = 0; c < 4; c++) acc[a][b][c] = 0.f;

    for (int s = 0; s < NST1; s++) {
        // fill: load fp32, split, store fp16 planes (no staging regs)
        #pragma unroll
        for (int i = 0; i < 4; i++) {
            int n = n0 + s * 32 + lrow[i];
            float4 vu, vx;
            if (n < N_NODES) {
                vu = *(const float4*)(U + (size_t)n * K_EIG + kt * 128 + lcol[i]);
                vx = *(const float4*)(x + (size_t)n * F_DIM + lcol[i]);
            } else {
                vu = make_float4(0.f, 0.f, 0.f, 0.f);
                vx = vu;
            }
            uint2 h, l;
            int off = lrow[i] * P1_STR + lcol[i];
            split4h(vu, h, l);
            *(uint2*)(smw + off)              = h;     // UH
            *(uint2*)(smw + P1_ASZ + off)     = l;     // UL
            *(uint2*)(smw + 2 * P1_ASZ + off) = round4h(vx);   // XH
        }
        __syncthreads();

        #pragma unroll
        for (int c = 0; c < 2; c++) {
            const unsigned nco = c * 16 * P1_STR;
            unsigned ah[4][4], al[4][4], bh[4][2];
            #pragma unroll
            for (int mt = 0; mt < 4; mt++) {
                LDSM_T(ah[mt], sbase + (nco + aoffs[mt]) * 2);
                LDSM_T(al[mt], sbase + (nco + P1_ASZ + aoffs[mt]) * 2);
            }
            #pragma unroll
            for (int blk = 0; blk < 2; blk++) {
                unsigned t[4];
                LDSM_T(t, sbase + (nco + 2 * P1_ASZ + boffs[blk]) * 2);
                bh[blk * 2][0] = t[0]; bh[blk * 2][1] = t[1];
                bh[blk * 2 + 1][0] = t[2]; bh[blk * 2 + 1][1] = t[3];
            }
            #pragma unroll
            for (int mt = 0; mt < 4; mt++)
                #pragma unroll
                for (int nt = 0; nt < 4; nt++) {
                    MMA16(acc[mt][nt], al[mt], bh[nt][0], bh[nt][1]);
                    MMA16(acc[mt][nt], ah[mt], bh[nt][0], bh[nt][1]);
                }
        }
        __syncthreads();
    }

    const int qr = lane >> 2, qc = lane & 3;
    float* pbase = g_partial + (size_t)ch * (K_EIG * F_DIM);
    #pragma unroll
    for (int mt = 0; mt < 4; mt++) {
        int m = wm * 64 + mt * 16 + qr;
        #pragma unroll
        for (int nt = 0; nt < 4; nt++) {
            int f  = wf * 32 + nt * 8 + 2 * qc;
            int kq = kt * 128 + m;
            __stwt((float2*)(pbase + (size_t)kq * F_DIM + f),
                   make_float2(acc[mt][nt][0], acc[mt][nt][1]));
            __stwt((float2*)(pbase + (size_t)(kq + 8) * F_DIM + f),
                   make_float2(acc[mt][nt][2], acc[mt][nt][3]));
        }
    }
}

// ---------------------------------------------------------------------------
// Phase 1.5: y = g[k]*sum_ch partial -> fp16 plane [k][f]
// ---------------------------------------------------------------------------
__global__ void phase15_kernel(const float* __restrict__ g) {
    int v = blockIdx.x * blockDim.x + threadIdx.x;
    int idx = v * 4;
    float4 s = make_float4(0.f, 0.f, 0.f, 0.f);
    #pragma unroll 8
    for (int c = 0; c < NC; c++) {
        float4 p = *(const float4*)(g_partial + (size_t)c * (K_EIG * F_DIM) + idx);
        s.x += p.x; s.y += p.y; s.z += p.z; s.w += p.w;
    }
    float gk = __ldg(&g[idx >> 7]);
    s.x *= gk; s.y *= gk; s.z *= gk; s.w *= gk;
    *(uint2*)(g_yh + idx) = round4h(s);
}

// ---------------------------------------------------------------------------
// Phase 2: out[n][f] = relu( sum_k U[n,k] * y[k,f] )
// Tile 64n x 128f, grid 782, 256 thr, 2 CTAs/SM. Warp tile 32x32.
// ---------------------------------------------------------------------------
__global__ void __launch_bounds__(256, 2)
phase2_kernel(const float* __restrict__ U, float* __restrict__ out) {
    extern __shared__ unsigned short smw[];
    const unsigned sbase = (unsigned)__cvta_generic_to_shared(smw);

    const int nb   = blockIdx.x * 64;
    const int tid  = threadIdx.x;
    const int lane = tid & 31;
    const int wid  = tid >> 5;
    const int wm   = wid >> 2;            // 0..1 (32 n each)
    const int wf   = wid & 3;             // 0..3 (32 f each)

    const int lr   = lane & 7;
    const int arow = ((lane >> 3) & 1) * 8 + lr;       // non-trans A
    const int acol = ((lane >> 4) & 1) * 8;
    const int brow = ((lane >> 3) & 1) * 8 + lr;       // trans B
    const int bcol = ((lane >> 4) & 1) * 8;
    unsigned aoffs[2], boffs[2];
    #pragma unroll
    for (int mt = 0; mt < 2; mt++)
        aoffs[mt] = (unsigned)((wm * 32 + mt * 16 + arow) * P2_USTR + acol);
    #pragma unroll
    for (int blk = 0; blk < 2; blk++)
        boffs[blk] = (unsigned)(brow * P2_YSTR + wf * 32 + blk * 16 + bcol);

    float acc[2][4][4];
    #pragma unroll
    for (int a = 0; a < 2; a++)
        #pragma unroll
        for (int b = 0; b < 4; b++)
            #pragma unroll
            for (int c = 0; c < 4; c++) acc[a][b][c] = 0.f;

    const int NST2 = K_EIG / 32;          // 16
    for (int s = 0; s < NST2; s++) {
        // U fill: [64n][32k], 512 float4 -> 2 per thread
        #pragma unroll
        for (int i = 0; i < 2; i++) {
            int task = tid + i * 256;          // 0..511
            int n  = task >> 3;                // 0..63
            int kq = task & 7;                 // float4 group within 32k
            int gn = nb + n;
            float4 v = (gn < N_NODES)
                     ? *(const float4*)(U + (size_t)gn * K_EIG + s * 32 + kq * 4)
                     : make_float4(0.f, 0.f, 0.f, 0.f);
            uint2 h, l;
            split4h(v, h, l);
            int uoff = n * P2_USTR + kq * 4;
            *(uint2*)(smw + uoff)          = h;    // UH
            *(uint2*)(smw + P2_USZ + uoff) = l;    // UL
        }
        // Y fill: [32k][128f] copy, 1024 uint2 -> 4 per thread
        #pragma unroll
        for (int i = 0; i < 4; i++) {
            int task = tid + i * 256;          // 0..1023
            int row = task >> 5;               // 0..31 (k)
            int q   = task & 31;               // uint2 col (4 f)
            *(uint2*)(smw + 2 * P2_USZ + row * P2_YSTR + q * 4) =
                *(const uint2*)(g_yh + (size_t)(s * 32 + row) * F_DIM + q * 4);
        }
        __syncthreads();

        #pragma unroll
        for (int c = 0; c < 2; c++) {
            unsigned ah[2][4], al[2][4], bh[4][2];
            #pragma unroll
            for (int mt = 0; mt < 2; mt++) {
                LDSM_N(ah[mt], sbase + (aoffs[mt] + c * 16) * 2);
                LDSM_N(al[mt], sbase + (P2_USZ + aoffs[mt] + c * 16) * 2);
            }
            #pragma unroll
            for (int blk = 0; blk < 2; blk++) {
                unsigned t[4];
                LDSM_T(t, sbase + (2 * P2_USZ + c * 16 * P2_YSTR + boffs[blk]) * 2);
                bh[blk * 2][0] = t[0]; bh[blk * 2][1] = t[1];
                bh[blk * 2 + 1][0] = t[2]; bh[blk * 2 + 1][1] = t[3];
            }
            #pragma unroll
            for (int mt = 0; mt < 2; mt++)
                #pragma unroll
                for (int nt = 0; nt < 4; nt++) {
                    MMA16(acc[mt][nt], al[mt], bh[nt][0], bh[nt][1]);
                    MMA16(acc[mt][nt], ah[mt], bh[nt][0], bh[nt][1]);
                }
        }
        __syncthreads();
    }

    const int qr = lane >> 2, qc = lane & 3;
    #pragma unroll
    for (int mt = 0; mt < 2; mt++) {
        int n = nb + wm * 32 + mt * 16 + qr;
        #pragma unroll
        for (int nt = 0; nt < 4; nt++) {
            int f = wf * 32 + nt * 8 + 2 * qc;
            if (n < N_NODES) {
                *(float2*)(out + (size_t)n * F_DIM + f) =
                    make_float2(fmaxf(acc[mt][nt][0], 0.f),
                                fmaxf(acc[mt][nt][1], 0.f));
            }
            if (n + 8 < N_NODES) {
                *(float2*)(out + (size_t)(n + 8) * F_DIM + f) =
                    make_float2(fmaxf(acc[mt][nt][2], 0.f),
                                fmaxf(acc[mt][nt][3], 0.f));
            }
        }
    }
}

// ---------------------------------------------------------------------------
extern "C" void kernel_launch(void* const* d_in, const int* in_sizes, int n_in,
                              void* d_out, int out_size) {
    const float* U = nullptr;
    const float* g = nullptr;
    const float* x = nullptr;
    for (int i = 0; i < n_in; i++) {
        if (in_sizes[i] == N_NODES * K_EIG)      U = (const float*)d_in[i];
        else if (in_sizes[i] == K_EIG)           g = (const float*)d_in[i];
        else if (in_sizes[i] == N_NODES * F_DIM) x = (const float*)d_in[i];
    }
    float* out = (float*)d_out;

    cudaFuncSetAttribute(phase1_kernel,
                         cudaFuncAttributeMaxDynamicSharedMemorySize, P1_SMEM);
    cudaFuncSetAttribute(phase2_kernel,
                         cudaFuncAttributeMaxDynamicSharedMemorySize, P2_SMEM);

    phase1_kernel<<<dim3(4, NC), 256, P1_SMEM>>>(U, x);
    phase15_kernel<<<(K_EIG * F_DIM) / 1024, 256>>>(g);
    phase2_kernel<<<(N_NODES + 63) / 64, 256, P2_SMEM>>>(U, out);
}